// round 14
// baseline (speedup 1.0000x reference)
#include <cuda_runtime.h>
#include <cuda_fp16.h>
#include <cstdint>

#define B_DIM   512
#define IN_DIM  4096
#define OUT_DIM 11008
#define KT      32
#define NIT     128          /* 4096 / 32 */
#define NC      80           /* output cols per CTA */
#define THREADS 512
#define GRID    138          /* ceil(11008/80) */

/* smem layout (bytes). fp16 tiles: row stride 80B. raw rows: 144B (16B-aligned, +4 bank shift) */
#define XS      40960        /* 512 rows * 80B          (per stage) */
#define WS      6400         /* 80 rows * 80B           (per stage) */
#define RROW    144          /* raw row stride */
#define RHALF   11520        /* 80 * 144 */
#define RS      23040        /* stored half + sign half (per stage) */
#define SM_XF   0            /* 2 * XS = 81920 */
#define SM_WF   81920        /* 2 * WS = 12800 */
#define SM_RAW  94720        /* 2 * RS = 46080 */
#define SM_BS   140800       /* 80 f32 */
#define SM_SC   141120       /* 80 f32 */
#define SMEM_BYTES 141440

__device__ __align__(16) uint32_t g_xh[(size_t)B_DIM * IN_DIM / 2];  /* x as fp16 */

static __device__ __forceinline__ uint32_t smem_u32(const void* p) {
    uint32_t a;
    asm("{ .reg .u64 t; cvta.to.shared.u64 t, %1; cvt.u32.u64 %0, t; }" : "=r"(a) : "l"(p));
    return a;
}
static __device__ __forceinline__ void cp16(uint32_t dst, const void* src) {
    asm volatile("cp.async.cg.shared.global [%0], [%1], 16;" :: "r"(dst), "l"(src) : "memory");
}
static __device__ __forceinline__ void cp_commit() {
    asm volatile("cp.async.commit_group;" ::: "memory");
}
static __device__ __forceinline__ void cp_wait0() {
    asm volatile("cp.async.wait_group 0;" ::: "memory");
}
static __device__ __forceinline__ void ldm_x4(uint32_t* r, uint32_t addr) {
    asm volatile("ldmatrix.sync.aligned.m8n8.x4.shared.b16 {%0,%1,%2,%3}, [%4];"
                 : "=r"(r[0]), "=r"(r[1]), "=r"(r[2]), "=r"(r[3]) : "r"(addr));
}
static __device__ __forceinline__ void ldm_x2(uint32_t* r, uint32_t addr) {
    asm volatile("ldmatrix.sync.aligned.m8n8.x2.shared.b16 {%0,%1}, [%2];"
                 : "=r"(r[0]), "=r"(r[1]) : "r"(addr));
}
static __device__ __forceinline__ void mma16816(float* c, const uint32_t* a, const uint32_t* b) {
    asm volatile("mma.sync.aligned.m16n8k16.row.col.f32.f16.f16.f32 "
                 "{%0,%1,%2,%3}, {%4,%5,%6,%7}, {%8,%9}, {%0,%1,%2,%3};"
                 : "+f"(c[0]), "+f"(c[1]), "+f"(c[2]), "+f"(c[3])
                 : "r"(a[0]), "r"(a[1]), "r"(a[2]), "r"(a[3]), "r"(b[0]), "r"(b[1]));
}

/* QINS dequant: t = 8388863 - as_float(0x4B000000|s) == 255-s EXACT; u = t*C1+LM2; w = 2^u */
static __device__ __forceinline__ uint32_t dq_pair(int s0, int g0, int s1, int g1,
                                                   float C1, float LM2) {
    const float K = 8388863.0f;
    float t0 = K - __uint_as_float(0x4B000000u | (uint32_t)s0);
    float t1 = K - __uint_as_float(0x4B000000u | (uint32_t)s1);
    float u0 = fmaf(t0, C1, LM2);
    float u1 = fmaf(t1, C1, LM2);
    float w0, w1;
    asm("ex2.approx.ftz.f32 %0, %1;" : "=f"(w0) : "f"(u0));
    asm("ex2.approx.ftz.f32 %0, %1;" : "=f"(w1) : "f"(u1));
    float v0 = __uint_as_float(__float_as_uint(w0) | ((uint32_t)g0 & 0x80000000u));
    float v1 = __uint_as_float(__float_as_uint(w1) | ((uint32_t)g1 & 0x80000000u));
    uint32_t h;
    asm("cvt.rn.f16x2.f32 %0, %1, %2;" : "=r"(h) : "f"(v1), "f"(v0));
    return h;
}

/* cp.async x fp16 tile, stage st, K-iter i.
   CONFLICT-FREE map: thread t = batch row t, seg j=0..3 -> one row per 8-thread
   STS phase (banks 0..31 distinct); gmem side reads 64B contiguous per thread. */
static __device__ __forceinline__ void fill_x(uint32_t sb, int st, int i) {
    const int t = threadIdx.x;
    const int kk = i * KT;
    const uint32_t dst0 = sb + SM_XF + (uint32_t)st * XS + (uint32_t)t * 80u;
    const char* src0 = (const char*)g_xh + ((size_t)t * IN_DIM + kk) * 2;
#pragma unroll
    for (int j = 0; j < 4; j++)
        cp16(dst0 + (uint32_t)j * 16u, src0 + j * 16);
}

/* cp.async raw stored+sign, stage st, K-iter i: 2 x 80 rows x 128B into 144B-stride rows */
static __device__ __forceinline__ void fill_raw(uint32_t sb, int st, int i, int nbase,
                                                const int* stored, const int* sgn) {
    const int t = threadIdx.x;
    const int kk = i * KT;
    const uint32_t dst0 = sb + SM_RAW + (uint32_t)st * RS;
#pragma unroll
    for (int j = 0; j < 3; j++) {
        int job = t + THREADS * j;
        if (job < 1280) {
            int arr = job >= 640;
            int jj = job - arr * 640;
            int row = jj >> 3, seg = jj & 7;
            int rowg = nbase + row; if (rowg >= OUT_DIM) rowg = 0;
            const int* src = (arr ? sgn : stored) + (size_t)rowg * IN_DIM + kk + seg * 4;
            uint32_t dst = dst0 + (uint32_t)arr * RHALF
                         + (uint32_t)row * RROW + (uint32_t)seg * 16u;
            cp16(dst, src);
        }
    }
}

/* dequant raw(st) -> fp16 W tile(st). 320 jobs of 8 elems; 144B stride -> conflict-free LDS */
static __device__ __forceinline__ void dequant(char* sm, int st, float C1, float LM2) {
    const int t = threadIdx.x;
    const char* raw = sm + SM_RAW + (size_t)st * RS;
    char* wf = sm + SM_WF + (size_t)st * WS;
    if (t < 320) {
        int r = t >> 2, q = t & 3;
        const int4* sp = (const int4*)(raw + (size_t)r * RROW + q * 32);
        const int4* gp = (const int4*)(raw + RHALF + (size_t)r * RROW + q * 32);
        int4 s0 = sp[0], s1 = sp[1];
        int4 g0 = gp[0], g1 = gp[1];
        uint4 o;
        o.x = dq_pair(s0.x, g0.x, s0.y, g0.y, C1, LM2);
        o.y = dq_pair(s0.z, g0.z, s0.w, g0.w, C1, LM2);
        o.z = dq_pair(s1.x, g1.x, s1.y, g1.y, C1, LM2);
        o.w = dq_pair(s1.z, g1.z, s1.w, g1.w, C1, LM2);
        *(uint4*)(wf + (size_t)r * 80 + q * 16) = o;
    }
}

__global__ void __launch_bounds__(THREADS, 1) qins_hmma_kernel(
    const int* __restrict__ stored, const int* __restrict__ sgn,
    const float* __restrict__ lmn, const float* __restrict__ lmx,
    const float* __restrict__ scale, const float* __restrict__ bias,
    float* __restrict__ out)
{
    extern __shared__ char sm[];
    const int t = threadIdx.x, wid = t >> 5, lane = t & 31;
    const int wm = wid & 7;          /* M 64-row block   */
    const int wn = wid >> 3;         /* N 40-col block   */
    const int nbase = blockIdx.x * NC;
    const uint32_t sb = smem_u32(sm);

    if (t < NC) {
        int c = nbase + t; if (c >= OUT_DIM) c = 0;
        ((float*)(sm + SM_BS))[t] = __ldg(bias + c);
        ((float*)(sm + SM_SC))[t] = __ldg(scale + c);
    }

    const float LOG2E = 1.44269504088896f;
    const float lm = __ldg(lmn), lxv = __ldg(lmx);
    const float C1  = (lxv - lm) * (1.0f / 254.0f) * LOG2E;
    const float LM2 = lm * LOG2E;

    float acc[4][5][4];
#pragma unroll
    for (int a = 0; a < 4; a++)
#pragma unroll
        for (int b = 0; b < 5; b++)
#pragma unroll
            for (int c = 0; c < 4; c++) acc[a][b][c] = 0.0f;

    /* prologue */
    fill_raw(sb, 0, 0, nbase, stored, sgn);
    fill_x(sb, 0, 0);
    cp_commit();
    cp_wait0();
    __syncthreads();
    dequant(sm, 0, C1, LM2);
    fill_raw(sb, 1, 1, nbase, stored, sgn);
    fill_x(sb, 1, 1);
    cp_commit();
    __syncthreads();          /* Wf(0) visible; stage1 in flight */

    const int grp = lane >> 3, rr = lane & 7;
    const int g2  = (lane >> 3) & 1;

    for (int i = 0; i < NIT; i++) {
        const int st = i & 1;
        const uint32_t xfb = sb + SM_XF + (uint32_t)st * XS;
        const uint32_t wfb = sb + SM_WF + (uint32_t)st * WS;

        /* ---- MMA over stage st: warp = 64 rows x 40 cols ---- */
#pragma unroll
        for (int ks = 0; ks < 2; ks++) {
            uint32_t bfr[5][2];
#pragma unroll
            for (int np = 0; np < 2; np++) {
                uint32_t r4[4];
                uint32_t addr = wfb
                    + (uint32_t)(wn * 40 + np * 16 + (grp >> 1) * 8 + rr) * 80u
                    + (uint32_t)ks * 32u + (uint32_t)(grp & 1) * 16u;
                ldm_x4(r4, addr);
                bfr[2 * np][0] = r4[0]; bfr[2 * np][1] = r4[1];
                bfr[2 * np + 1][0] = r4[2]; bfr[2 * np + 1][1] = r4[3];
            }
            {
                uint32_t r2[2];
                uint32_t addr = wfb
                    + (uint32_t)(wn * 40 + 32 + rr) * 80u
                    + (uint32_t)ks * 32u + (uint32_t)g2 * 16u;
                ldm_x2(r2, addr);
                bfr[4][0] = r2[0]; bfr[4][1] = r2[1];
            }
#pragma unroll
            for (int mt = 0; mt < 4; mt++) {
                uint32_t afr[4];
                uint32_t addr = xfb
                    + (uint32_t)(wm * 64 + mt * 16 + (grp & 1) * 8 + rr) * 80u
                    + (uint32_t)ks * 32u + (uint32_t)(grp >> 1) * 16u;
                ldm_x4(afr, addr);
#pragma unroll
                for (int nt = 0; nt < 5; nt++)
                    mma16816(acc[mt][nt], afr, bfr[nt]);
            }
        }

        /* ---- pipeline maintenance ---- */
        cp_wait0();            /* raw/x for stage st^1 (iter i+1) arrived */
        __syncthreads();       /* all warps done with mma(st); arrivals visible */
        if (i + 1 < NIT) dequant(sm, st ^ 1, C1, LM2);
        if (i + 2 < NIT) {
            fill_raw(sb, st, i + 2, nbase, stored, sgn);
            fill_x(sb, st, i + 2);
            cp_commit();
        }
        __syncthreads();       /* Wf(st^1) visible before next iter */
    }

    /* ---- epilogue ---- */
    const float* bs = (const float*)(sm + SM_BS);
    const float* scp = (const float*)(sm + SM_SC);
    const int r0 = lane >> 2, c0 = (lane & 3) * 2;
#pragma unroll
    for (int mt = 0; mt < 4; mt++) {
#pragma unroll
        for (int nt = 0; nt < 5; nt++) {
            int colL = wn * 40 + nt * 8 + c0;
            int colg = nbase + colL;
            if (colg < OUT_DIM) {
                float b0 = bs[colL], b1 = bs[colL + 1];
                float s0f = scp[colL], s1f = scp[colL + 1];
                int m0 = wm * 64 + mt * 16 + r0;
                float2 v0 = make_float2((acc[mt][nt][0] + b0) * s0f,
                                        (acc[mt][nt][1] + b1) * s1f);
                float2 v1 = make_float2((acc[mt][nt][2] + b0) * s0f,
                                        (acc[mt][nt][3] + b1) * s1f);
                *(float2*)(out + (size_t)m0 * OUT_DIM + colg) = v0;
                *(float2*)(out + (size_t)(m0 + 8) * OUT_DIM + colg) = v1;
            }
        }
    }
}

__global__ void xconv_kernel(const float* __restrict__ x) {
    const uint32_t i = blockIdx.x * 512u + threadIdx.x;   /* 1048576 total */
    float2 v = ((const float2*)x)[i];
    __half2 h = __floats2half2_rn(v.x, v.y);
    g_xh[i] = *(uint32_t*)&h;
}

extern "C" void kernel_launch(void* const* d_in, const int* in_sizes, int n_in,
                              void* d_out, int out_size) {
    const float* x      = (const float*)d_in[0];
    const int*   stored = (const int*)d_in[1];
    const int*   sgn    = (const int*)d_in[2];
    const float* lmn    = (const float*)d_in[3];
    const float* lmx    = (const float*)d_in[4];
    const float* scale  = (const float*)d_in[5];
    const float* bias   = (const float*)d_in[6];
    float* out = (float*)d_out;

    cudaFuncSetAttribute(qins_hmma_kernel,
                         cudaFuncAttributeMaxDynamicSharedMemorySize, SMEM_BYTES);
    xconv_kernel<<<2048, 512>>>(x);
    qins_hmma_kernel<<<GRID, THREADS, SMEM_BYTES>>>(stored, sgn, lmn, lmx, scale, bias, out);
}

// round 15
// speedup vs baseline: 1.3111x; 1.3111x over previous
#include <cuda_runtime.h>
#include <cuda_fp16.h>
#include <cstdint>

#define B_DIM   512
#define IN_DIM  4096
#define OUT_DIM 11008
#define KT      32
#define NIT     128          /* 4096 / 32 */
#define NC      80           /* output cols per CTA */
#define THREADS 512
#define GRID    138          /* ceil(11008/80) */

/* smem layout (bytes). fp16 tiles: row stride 80B. raw rows: 144B (16B-aligned, +4 bank shift) */
#define XS      40960        /* 512 rows * 80B          (per stage) */
#define WS      6400         /* 80 rows * 80B           (per stage) */
#define RROW    144          /* raw row stride */
#define RHALF   11520        /* 80 * 144 */
#define RS      23040        /* stored half + sign half (per stage) */
#define SM_XF   0            /* 2 * XS = 81920 */
#define SM_WF   81920        /* 2 * WS = 12800 */
#define SM_RAW  94720        /* 2 * RS = 46080 */
#define SM_BS   140800       /* 80 f32 */
#define SM_SC   141120       /* 80 f32 */
#define SMEM_BYTES 141440

__device__ __align__(16) uint32_t g_xh[(size_t)B_DIM * IN_DIM / 2];  /* x as fp16 */

static __device__ __forceinline__ uint32_t smem_u32(const void* p) {
    uint32_t a;
    asm("{ .reg .u64 t; cvta.to.shared.u64 t, %1; cvt.u32.u64 %0, t; }" : "=r"(a) : "l"(p));
    return a;
}
static __device__ __forceinline__ void cp16(uint32_t dst, const void* src) {
    asm volatile("cp.async.cg.shared.global [%0], [%1], 16;" :: "r"(dst), "l"(src) : "memory");
}
static __device__ __forceinline__ void cp_commit() {
    asm volatile("cp.async.commit_group;" ::: "memory");
}
static __device__ __forceinline__ void cp_wait0() {
    asm volatile("cp.async.wait_group 0;" ::: "memory");
}
static __device__ __forceinline__ void ldm_x4(uint32_t* r, uint32_t addr) {
    asm volatile("ldmatrix.sync.aligned.m8n8.x4.shared.b16 {%0,%1,%2,%3}, [%4];"
                 : "=r"(r[0]), "=r"(r[1]), "=r"(r[2]), "=r"(r[3]) : "r"(addr));
}
static __device__ __forceinline__ void ldm_x2(uint32_t* r, uint32_t addr) {
    asm volatile("ldmatrix.sync.aligned.m8n8.x2.shared.b16 {%0,%1}, [%2];"
                 : "=r"(r[0]), "=r"(r[1]) : "r"(addr));
}
static __device__ __forceinline__ void mma16816(float* c, const uint32_t* a, const uint32_t* b) {
    asm volatile("mma.sync.aligned.m16n8k16.row.col.f32.f16.f16.f32 "
                 "{%0,%1,%2,%3}, {%4,%5,%6,%7}, {%8,%9}, {%0,%1,%2,%3};"
                 : "+f"(c[0]), "+f"(c[1]), "+f"(c[2]), "+f"(c[3])
                 : "r"(a[0]), "r"(a[1]), "r"(a[2]), "r"(a[3]), "r"(b[0]), "r"(b[1]));
}

/* QINS dequant: t = 8388863 - as_float(0x4B000000|s) == 255-s EXACT; u = t*C1+LM2; w = 2^u */
static __device__ __forceinline__ uint32_t dq_pair(int s0, int g0, int s1, int g1,
                                                   float C1, float LM2) {
    const float K = 8388863.0f;
    float t0 = K - __uint_as_float(0x4B000000u | (uint32_t)s0);
    float t1 = K - __uint_as_float(0x4B000000u | (uint32_t)s1);
    float u0 = fmaf(t0, C1, LM2);
    float u1 = fmaf(t1, C1, LM2);
    float w0, w1;
    asm("ex2.approx.ftz.f32 %0, %1;" : "=f"(w0) : "f"(u0));
    asm("ex2.approx.ftz.f32 %0, %1;" : "=f"(w1) : "f"(u1));
    float v0 = __uint_as_float(__float_as_uint(w0) | ((uint32_t)g0 & 0x80000000u));
    float v1 = __uint_as_float(__float_as_uint(w1) | ((uint32_t)g1 & 0x80000000u));
    uint32_t h;
    asm("cvt.rn.f16x2.f32 %0, %1, %2;" : "=r"(h) : "f"(v1), "f"(v0));
    return h;
}

/* cp.async x fp16 tile, stage st, K-iter i: R6 map (4 lanes per row, 64B coalesced runs) */
static __device__ __forceinline__ void fill_x(uint32_t sb, int st, int i) {
    const int t = threadIdx.x;
    const int kk = i * KT;
    const uint32_t dst0 = sb + SM_XF + (uint32_t)st * XS;
#pragma unroll
    for (int j = 0; j < 4; j++) {
        int job = t + THREADS * j;
        int row = job >> 2, seg = job & 3;
        uint32_t dst = dst0 + (uint32_t)row * 80u + (uint32_t)seg * 16u;
        const char* src = (const char*)g_xh + ((size_t)row * IN_DIM + kk) * 2 + seg * 16;
        cp16(dst, src);
    }
}

/* cp.async raw stored+sign, stage st, K-iter i: 2 x 80 rows x 128B into 144B-stride rows */
static __device__ __forceinline__ void fill_raw(uint32_t sb, int st, int i, int nbase,
                                                const int* stored, const int* sgn) {
    const int t = threadIdx.x;
    const int kk = i * KT;
    const uint32_t dst0 = sb + SM_RAW + (uint32_t)st * RS;
#pragma unroll
    for (int j = 0; j < 3; j++) {
        int job = t + THREADS * j;
        if (job < 1280) {
            int arr = job >= 640;
            int jj = job - arr * 640;
            int row = jj >> 3, seg = jj & 7;
            int rowg = nbase + row; if (rowg >= OUT_DIM) rowg = 0;
            const int* src = (arr ? sgn : stored) + (size_t)rowg * IN_DIM + kk + seg * 4;
            uint32_t dst = dst0 + (uint32_t)arr * RHALF
                         + (uint32_t)row * RROW + (uint32_t)seg * 16u;
            cp16(dst, src);
        }
    }
}

/* dequant raw(st) -> fp16 W tile(st). 320 jobs of 8 elems; 144B stride -> conflict-free LDS */
static __device__ __forceinline__ void dequant(char* sm, int st, float C1, float LM2) {
    const int t = threadIdx.x;
    const char* raw = sm + SM_RAW + (size_t)st * RS;
    char* wf = sm + SM_WF + (size_t)st * WS;
    if (t < 320) {
        int r = t >> 2, q = t & 3;
        const int4* sp = (const int4*)(raw + (size_t)r * RROW + q * 32);
        const int4* gp = (const int4*)(raw + RHALF + (size_t)r * RROW + q * 32);
        int4 s0 = sp[0], s1 = sp[1];
        int4 g0 = gp[0], g1 = gp[1];
        uint4 o;
        o.x = dq_pair(s0.x, g0.x, s0.y, g0.y, C1, LM2);
        o.y = dq_pair(s0.z, g0.z, s0.w, g0.w, C1, LM2);
        o.z = dq_pair(s1.x, g1.x, s1.y, g1.y, C1, LM2);
        o.w = dq_pair(s1.z, g1.z, s1.w, g1.w, C1, LM2);
        *(uint4*)(wf + (size_t)r * 80 + q * 16) = o;
    }
}

__global__ void __launch_bounds__(THREADS, 1) qins_hmma_kernel(
    const int* __restrict__ stored, const int* __restrict__ sgn,
    const float* __restrict__ lmn, const float* __restrict__ lmx,
    const float* __restrict__ scale, const float* __restrict__ bias,
    float* __restrict__ out)
{
    extern __shared__ char sm[];
    const int t = threadIdx.x, wid = t >> 5, lane = t & 31;
    const int wm = wid & 7;          /* M 64-row block   */
    const int wn = wid >> 3;         /* N 40-col block   */
    const int nbase = blockIdx.x * NC;
    const uint32_t sb = smem_u32(sm);

    if (t < NC) {
        int c = nbase + t; if (c >= OUT_DIM) c = 0;
        ((float*)(sm + SM_BS))[t] = __ldg(bias + c);
        ((float*)(sm + SM_SC))[t] = __ldg(scale + c);
    }

    const float LOG2E = 1.44269504088896f;
    const float lm = __ldg(lmn), lxv = __ldg(lmx);
    const float C1  = (lxv - lm) * (1.0f / 254.0f) * LOG2E;
    const float LM2 = lm * LOG2E;

    float acc[4][5][4];
#pragma unroll
    for (int a = 0; a < 4; a++)
#pragma unroll
        for (int b = 0; b < 5; b++)
#pragma unroll
            for (int c = 0; c < 4; c++) acc[a][b][c] = 0.0f;

    /* prologue */
    fill_raw(sb, 0, 0, nbase, stored, sgn);
    fill_x(sb, 0, 0);
    cp_commit();
    cp_wait0();
    __syncthreads();
    dequant(sm, 0, C1, LM2);
    fill_raw(sb, 1, 1, nbase, stored, sgn);
    fill_x(sb, 1, 1);
    cp_commit();
    __syncthreads();          /* Wf(0) visible; stage1 in flight */

    const int grp = lane >> 3, rr = lane & 7;
    const int g2  = (lane >> 3) & 1;

    for (int i = 0; i < NIT; i++) {
        const int st = i & 1;
        const uint32_t xfb = sb + SM_XF + (uint32_t)st * XS;
        const uint32_t wfb = sb + SM_WF + (uint32_t)st * WS;

        /* ---- MMA over stage st: warp = 64 rows x 40 cols ---- */
#pragma unroll
        for (int ks = 0; ks < 2; ks++) {
            uint32_t bfr[5][2];
#pragma unroll
            for (int np = 0; np < 2; np++) {
                uint32_t r4[4];
                uint32_t addr = wfb
                    + (uint32_t)(wn * 40 + np * 16 + (grp >> 1) * 8 + rr) * 80u
                    + (uint32_t)ks * 32u + (uint32_t)(grp & 1) * 16u;
                ldm_x4(r4, addr);
                bfr[2 * np][0] = r4[0]; bfr[2 * np][1] = r4[1];
                bfr[2 * np + 1][0] = r4[2]; bfr[2 * np + 1][1] = r4[3];
            }
            {
                uint32_t r2[2];
                uint32_t addr = wfb
                    + (uint32_t)(wn * 40 + 32 + rr) * 80u
                    + (uint32_t)ks * 32u + (uint32_t)g2 * 16u;
                ldm_x2(r2, addr);
                bfr[4][0] = r2[0]; bfr[4][1] = r2[1];
            }
#pragma unroll
            for (int mt = 0; mt < 4; mt++) {
                uint32_t afr[4];
                uint32_t addr = xfb
                    + (uint32_t)(wm * 64 + mt * 16 + (grp & 1) * 8 + rr) * 80u
                    + (uint32_t)ks * 32u + (uint32_t)(grp >> 1) * 16u;
                ldm_x4(afr, addr);
#pragma unroll
                for (int nt = 0; nt < 5; nt++)
                    mma16816(acc[mt][nt], afr, bfr[nt]);
            }
        }

        /* ---- pipeline maintenance ---- */
        cp_wait0();            /* raw/x for stage st^1 (iter i+1) arrived */
        __syncthreads();       /* all warps done with mma(st); arrivals visible */
        if (i + 1 < NIT) dequant(sm, st ^ 1, C1, LM2);
        if (i + 2 < NIT) {
            fill_raw(sb, st, i + 2, nbase, stored, sgn);
            fill_x(sb, st, i + 2);
            cp_commit();
        }
        __syncthreads();       /* Wf(st^1) visible before next iter */
    }

    /* ---- epilogue ---- */
    const float* bs = (const float*)(sm + SM_BS);
    const float* scp = (const float*)(sm + SM_SC);
    const int r0 = lane >> 2, c0 = (lane & 3) * 2;
#pragma unroll
    for (int mt = 0; mt < 4; mt++) {
#pragma unroll
        for (int nt = 0; nt < 5; nt++) {
            int colL = wn * 40 + nt * 8 + c0;
            int colg = nbase + colL;
            if (colg < OUT_DIM) {
                float b0 = bs[colL], b1 = bs[colL + 1];
                float s0f = scp[colL], s1f = scp[colL + 1];
                int m0 = wm * 64 + mt * 16 + r0;
                float2 v0 = make_float2((acc[mt][nt][0] + b0) * s0f,
                                        (acc[mt][nt][1] + b1) * s1f);
                float2 v1 = make_float2((acc[mt][nt][2] + b0) * s0f,
                                        (acc[mt][nt][3] + b1) * s1f);
                *(float2*)(out + (size_t)m0 * OUT_DIM + colg) = v0;
                *(float2*)(out + (size_t)(m0 + 8) * OUT_DIM + colg) = v1;
            }
        }
    }
}

__global__ void xconv_kernel(const float* __restrict__ x) {
    const uint32_t i = blockIdx.x * 512u + threadIdx.x;   /* 1048576 total */
    float2 v = ((const float2*)x)[i];
    __half2 h = __floats2half2_rn(v.x, v.y);
    g_xh[i] = *(uint32_t*)&h;
}

extern "C" void kernel_launch(void* const* d_in, const int* in_sizes, int n_in,
                              void* d_out, int out_size) {
    const float* x      = (const float*)d_in[0];
    const int*   stored = (const int*)d_in[1];
    const int*   sgn    = (const int*)d_in[2];
    const float* lmn    = (const float*)d_in[3];
    const float* lmx    = (const float*)d_in[4];
    const float* scale  = (const float*)d_in[5];
    const float* bias   = (const float*)d_in[6];
    float* out = (float*)d_out;

    cudaFuncSetAttribute(qins_hmma_kernel,
                         cudaFuncAttributeMaxDynamicSharedMemorySize, SMEM_BYTES);
    xconv_kernel<<<2048, 512>>>(x);
    qins_hmma_kernel<<<GRID, THREADS, SMEM_BYTES>>>(stored, sgn, lmn, lmx, scale, bias, out);
}

// round 16
// speedup vs baseline: 1.5017x; 1.1455x over previous
#include <cuda_runtime.h>
#include <cuda_fp16.h>
#include <cstdint>

#define B_DIM   512
#define IN_DIM  4096
#define OUT_DIM 11008
#define KT      32
#define NIT     128          /* 4096 / 32 */
#define NC      80           /* output cols per CTA */
#define THREADS 512
#define GRID    138          /* ceil(11008/80) */

/* smem layout (bytes). x: 3 stages. W: 2 stages. raw: 2 stages, 144B rows. */
#define XS      40960        /* 512 rows * 80B */
#define WS      6400         /* 80 rows * 80B  */
#define RROW    144
#define RHALF   11520        /* 80 * 144 */
#define RS      23040
#define SM_XF   0            /* 3 * XS = 122880 */
#define SM_WF   122880       /* 2 * WS = 12800  */
#define SM_RAW  135680       /* 2 * RS = 46080  */
#define SM_BS   181760
#define SM_SC   182080
#define SMEM_BYTES 182400

__device__ __align__(16) uint32_t g_xh[(size_t)B_DIM * IN_DIM / 2];  /* x as fp16 */

static __device__ __forceinline__ uint32_t smem_u32(const void* p) {
    uint32_t a;
    asm("{ .reg .u64 t; cvta.to.shared.u64 t, %1; cvt.u32.u64 %0, t; }" : "=r"(a) : "l"(p));
    return a;
}
static __device__ __forceinline__ void cp16(uint32_t dst, const void* src) {
    asm volatile("cp.async.cg.shared.global [%0], [%1], 16;" :: "r"(dst), "l"(src) : "memory");
}
static __device__ __forceinline__ void cp_commit() {
    asm volatile("cp.async.commit_group;" ::: "memory");
}
static __device__ __forceinline__ void cp_wait0() {
    asm volatile("cp.async.wait_group 0;" ::: "memory");
}
static __device__ __forceinline__ void ldm_x4(uint32_t* r, uint32_t addr) {
    asm volatile("ldmatrix.sync.aligned.m8n8.x4.shared.b16 {%0,%1,%2,%3}, [%4];"
                 : "=r"(r[0]), "=r"(r[1]), "=r"(r[2]), "=r"(r[3]) : "r"(addr));
}
static __device__ __forceinline__ void ldm_x2(uint32_t* r, uint32_t addr) {
    asm volatile("ldmatrix.sync.aligned.m8n8.x2.shared.b16 {%0,%1}, [%2];"
                 : "=r"(r[0]), "=r"(r[1]) : "r"(addr));
}
static __device__ __forceinline__ void mma16816(float* c, const uint32_t* a, const uint32_t* b) {
    asm volatile("mma.sync.aligned.m16n8k16.row.col.f32.f16.f16.f32 "
                 "{%0,%1,%2,%3}, {%4,%5,%6,%7}, {%8,%9}, {%0,%1,%2,%3};"
                 : "+f"(c[0]), "+f"(c[1]), "+f"(c[2]), "+f"(c[3])
                 : "r"(a[0]), "r"(a[1]), "r"(a[2]), "r"(a[3]), "r"(b[0]), "r"(b[1]));
}

/* QINS dequant: t = 8388863 - as_float(0x4B000000|s) == 255-s EXACT; u = t*C1+LM2; w = 2^u */
static __device__ __forceinline__ uint32_t dq_pair(int s0, int g0, int s1, int g1,
                                                   float C1, float LM2) {
    const float K = 8388863.0f;
    float t0 = K - __uint_as_float(0x4B000000u | (uint32_t)s0);
    float t1 = K - __uint_as_float(0x4B000000u | (uint32_t)s1);
    float u0 = fmaf(t0, C1, LM2);
    float u1 = fmaf(t1, C1, LM2);
    float w0, w1;
    asm("ex2.approx.ftz.f32 %0, %1;" : "=f"(w0) : "f"(u0));
    asm("ex2.approx.ftz.f32 %0, %1;" : "=f"(w1) : "f"(u1));
    float v0 = __uint_as_float(__float_as_uint(w0) | ((uint32_t)g0 & 0x80000000u));
    float v1 = __uint_as_float(__float_as_uint(w1) | ((uint32_t)g1 & 0x80000000u));
    uint32_t h;
    asm("cvt.rn.f16x2.f32 %0, %1, %2;" : "=r"(h) : "f"(v1), "f"(v0));
    return h;
}

/* x fp16 tile of K-iter k -> slot k%3: R6 coalesced map, 4 cp16/thread */
static __device__ __forceinline__ void fill_x(uint32_t sb, int k) {
    const int t = threadIdx.x;
    const int kk = k * KT;
    const uint32_t dst0 = sb + SM_XF + (uint32_t)(k % 3) * XS;
#pragma unroll
    for (int j = 0; j < 4; j++) {
        int job = t + THREADS * j;
        int row = job >> 2, seg = job & 3;
        uint32_t dst = dst0 + (uint32_t)row * 80u + (uint32_t)seg * 16u;
        const char* src = (const char*)g_xh + ((size_t)row * IN_DIM + kk) * 2 + seg * 16;
        cp16(dst, src);
    }
}

/* SELF-OWNED raw fetch: thread fetches exactly the 8 stored + 8 sign ints it dequants.
   u in 0..159, row = rbase + (u>>2), 8 cols at (u&3)*8. 4 cp16. */
static __device__ __forceinline__ void fill_raw_own(uint32_t sb, int k, int nbase,
                                                    int rbase, int u,
                                                    const int* stored, const int* sgn) {
    const int r = rbase + (u >> 2), q = u & 3;
    const int kk = k * KT;
    int rowg = nbase + r; if (rowg >= OUT_DIM) rowg = 0;
    const uint32_t dst = sb + SM_RAW + (uint32_t)(k & 1) * RS
                       + (uint32_t)r * RROW + (uint32_t)q * 32u;
    const int* ss = stored + (size_t)rowg * IN_DIM + kk + q * 8;
    const int* gg = sgn + (size_t)rowg * IN_DIM + kk + q * 8;
    cp16(dst, ss);            cp16(dst + 16u, ss + 4);
    cp16(dst + RHALF, gg);    cp16(dst + RHALF + 16u, gg + 4);
}

/* SELF-OWNED dequant of K-iter k: raw stage k&1 -> W stage k&1 */
static __device__ __forceinline__ void dequant_own(char* sm, int k, int rbase, int u,
                                                   float C1, float LM2) {
    const int r = rbase + (u >> 2), q = u & 3;
    const char* raw = sm + SM_RAW + (size_t)(k & 1) * RS;
    char* wf = sm + SM_WF + (size_t)(k & 1) * WS;
    const int4* sp = (const int4*)(raw + (size_t)r * RROW + q * 32);
    const int4* gp = (const int4*)(raw + RHALF + (size_t)r * RROW + q * 32);
    int4 s0 = sp[0], s1 = sp[1];
    int4 g0 = gp[0], g1 = gp[1];
    uint4 o;
    o.x = dq_pair(s0.x, g0.x, s0.y, g0.y, C1, LM2);
    o.y = dq_pair(s0.z, g0.z, s0.w, g0.w, C1, LM2);
    o.z = dq_pair(s1.x, g1.x, s1.y, g1.y, C1, LM2);
    o.w = dq_pair(s1.z, g1.z, s1.w, g1.w, C1, LM2);
    *(uint4*)(wf + (size_t)r * 80 + q * 16) = o;
}

/* produce step for iter i: wait fill(i+1), dequant(i+1), issue fill(i+2) */
static __device__ __forceinline__ void produce(char* sm, uint32_t sb, int i, int nbase,
                                               int rbase, int u, bool dq_on,
                                               const int* stored, const int* sgn,
                                               float C1, float LM2) {
    cp_wait0();
    if (dq_on && i + 1 < NIT) dequant_own(sm, i + 1, rbase, u, C1, LM2);
    if (i + 2 < NIT) {
        if (dq_on) fill_raw_own(sb, i + 2, nbase, rbase, u, stored, sgn);
        fill_x(sb, i + 2);
        cp_commit();
    }
}

/* one full MMA step over K-iter i */
static __device__ __forceinline__ void mma_step(uint32_t sb, int i, int wm, int wn,
                                                int grp, int rr, int g2,
                                                float acc[4][5][4]) {
    const uint32_t xfb = sb + SM_XF + (uint32_t)(i % 3) * XS;
    const uint32_t wfb = sb + SM_WF + (uint32_t)(i & 1) * WS;
#pragma unroll
    for (int ks = 0; ks < 2; ks++) {
        uint32_t bfr[5][2];
#pragma unroll
        for (int np = 0; np < 2; np++) {
            uint32_t r4[4];
            uint32_t addr = wfb
                + (uint32_t)(wn * 40 + np * 16 + (grp >> 1) * 8 + rr) * 80u
                + (uint32_t)ks * 32u + (uint32_t)(grp & 1) * 16u;
            ldm_x4(r4, addr);
            bfr[2 * np][0] = r4[0]; bfr[2 * np][1] = r4[1];
            bfr[2 * np + 1][0] = r4[2]; bfr[2 * np + 1][1] = r4[3];
        }
        {
            uint32_t r2[2];
            uint32_t addr = wfb
                + (uint32_t)(wn * 40 + 32 + rr) * 80u
                + (uint32_t)ks * 32u + (uint32_t)g2 * 16u;
            ldm_x2(r2, addr);
            bfr[4][0] = r2[0]; bfr[4][1] = r2[1];
        }
#pragma unroll
        for (int mt = 0; mt < 4; mt++) {
            uint32_t afr[4];
            uint32_t addr = xfb
                + (uint32_t)(wm * 64 + mt * 16 + (grp & 1) * 8 + rr) * 80u
                + (uint32_t)ks * 32u + (uint32_t)(grp >> 1) * 16u;
            ldm_x4(afr, addr);
#pragma unroll
            for (int nt = 0; nt < 5; nt++)
                mma16816(acc[mt][nt], afr, bfr[nt]);
        }
    }
}

__global__ void __launch_bounds__(THREADS, 1) qins_hmma_kernel(
    const int* __restrict__ stored, const int* __restrict__ sgn,
    const float* __restrict__ lmn, const float* __restrict__ lmx,
    const float* __restrict__ scale, const float* __restrict__ bias,
    float* __restrict__ out)
{
    extern __shared__ char sm[];
    const int t = threadIdx.x, wid = t >> 5, lane = t & 31;
    const int wm = wid & 7;          /* M 64-row block */
    const int wn = wid >> 3;         /* N 40-col block; also the skew group id */
    const int nbase = blockIdx.x * NC;
    const uint32_t sb = smem_u32(sm);

    if (t < NC) {
        int c = nbase + t; if (c >= OUT_DIM) c = 0;
        ((float*)(sm + SM_BS))[t] = __ldg(bias + c);
        ((float*)(sm + SM_SC))[t] = __ldg(scale + c);
    }

    const float LOG2E = 1.44269504088896f;
    const float lm = __ldg(lmn), lxv = __ldg(lmx);
    const float C1  = (lxv - lm) * (1.0f / 254.0f) * LOG2E;
    const float LM2 = lm * LOG2E;

    /* skew-group bookkeeping: A = warps 0-7 (wn=0, W rows 0-39), B = warps 8-15 */
    const bool grpA = (wn == 0);
    const int  u     = grpA ? t : (t - 256);   /* 0..255 within group */
    const bool dq_on = (u < 160);              /* 160 dq threads per group */
    const int  rbase = grpA ? 0 : 40;

    float acc[4][5][4];
#pragma unroll
    for (int a = 0; a < 4; a++)
#pragma unroll
        for (int b = 0; b < 5; b++)
#pragma unroll
            for (int c = 0; c < 4; c++) acc[a][b][c] = 0.0f;

    /* prologue: fetch tiles 0 and 1, dequant tile 0 (self-owned, no bar needed pre-dequant) */
    if (dq_on) fill_raw_own(sb, 0, nbase, rbase, u, stored, sgn);
    fill_x(sb, 0);
    cp_commit();
    if (dq_on) fill_raw_own(sb, 1, nbase, rbase, u, stored, sgn);
    fill_x(sb, 1);
    cp_commit();
    cp_wait0();
    if (dq_on) dequant_own(sm, 0, rbase, u, C1, LM2);
    __syncthreads();               /* publish x(0), x(1), W(0) */

    const int grp = lane >> 3, rr = lane & 7;
    const int g2  = (lane >> 3) & 1;

    for (int i = 0; i < NIT; i++) {
        if (grpA) {
            produce(sm, sb, i, nbase, rbase, u, dq_on, stored, sgn, C1, LM2);
            mma_step(sb, i, wm, wn, grp, rr, g2, acc);
        } else {
            mma_step(sb, i, wm, wn, grp, rr, g2, acc);
            produce(sm, sb, i, nbase, rbase, u, dq_on, stored, sgn, C1, LM2);
        }
        __syncthreads();           /* single barrier: publish W(i+1), x(i+2) */
    }

    /* ---- epilogue ---- */
    const float* bs = (const float*)(sm + SM_BS);
    const float* scp = (const float*)(sm + SM_SC);
    const int r0 = lane >> 2, c0 = (lane & 3) * 2;
#pragma unroll
    for (int mt = 0; mt < 4; mt++) {
#pragma unroll
        for (int nt = 0; nt < 5; nt++) {
            int colL = wn * 40 + nt * 8 + c0;
            int colg = nbase + colL;
            if (colg < OUT_DIM) {
                float b0 = bs[colL], b1 = bs[colL + 1];
                float s0f = scp[colL], s1f = scp[colL + 1];
                int m0 = wm * 64 + mt * 16 + r0;
                float2 v0 = make_float2((acc[mt][nt][0] + b0) * s0f,
                                        (acc[mt][nt][1] + b1) * s1f);
                float2 v1 = make_float2((acc[mt][nt][2] + b0) * s0f,
                                        (acc[mt][nt][3] + b1) * s1f);
                *(float2*)(out + (size_t)m0 * OUT_DIM + colg) = v0;
                *(float2*)(out + (size_t)(m0 + 8) * OUT_DIM + colg) = v1;
            }
        }
    }
}

__global__ void xconv_kernel(const float* __restrict__ x) {
    const uint32_t i = blockIdx.x * 512u + threadIdx.x;   /* 1048576 total */
    float2 v = ((const float2*)x)[i];
    __half2 h = __floats2half2_rn(v.x, v.y);
    g_xh[i] = *(uint32_t*)&h;
}

extern "C" void kernel_launch(void* const* d_in, const int* in_sizes, int n_in,
                              void* d_out, int out_size) {
    const float* x      = (const float*)d_in[0];
    const int*   stored = (const int*)d_in[1];
    const int*   sgn    = (const int*)d_in[2];
    const float* lmn    = (const float*)d_in[3];
    const float* lmx    = (const float*)d_in[4];
    const float* scale  = (const float*)d_in[5];
    const float* bias   = (const float*)d_in[6];
    float* out = (float*)d_out;

    cudaFuncSetAttribute(qins_hmma_kernel,
                         cudaFuncAttributeMaxDynamicSharedMemorySize, SMEM_BYTES);
    xconv_kernel<<<2048, 512>>>(x);
    qins_hmma_kernel<<<GRID, THREADS, SMEM_BYTES>>>(stored, sgn, lmn, lmx, scale, bias, out);
}